// round 15
// baseline (speedup 1.0000x reference)
#include <cuda_runtime.h>
#include <cuda_bf16.h>
#include <stdint.h>
#include <math.h>

// RecognitionODERNN: B=256, T=96, OBS=64, LATENT=256, HID=512, N_SUB=3
//
// 2-CTA clusters x 64 = 128 CTAs, 1024 thr/CTA (8 warps/SMSP), 4 batch rows
// per cluster. Rank r owns hid cols [r*256,+256) (phase A) and K-rows
// [r*256,+256) (phase B); phase-B partials exchanged via DSMEM
// (double-buffered mbarrier release/acquire).
//
// R15 = R12's efficient inner loop (4 cols/thread, LDG.128, 8 FFMA2/k,
// 0.69 issues/MAC) at 1024 threads via a 16-way K split (KSPAN halves,
// 8 warps/SMSP hide post-barrier L2 latency), + fast MUFU tanh.

#define TSEQ  96
#define OBSD  64
#define LAT   256
#define HIDD  512
#define KRNN  320
#define ROWS  4
#define TPB   1024
#define NCTA  128
#define HHALF 256     // hid cols per CTA
#define NSL   16      // K slices per phase
#define NC    256     // output cols per phase per CTA

typedef unsigned long long u64;
typedef unsigned int u32;

__device__ __forceinline__ u64 pk2(float x, float y) {
    u64 r; asm("mov.b64 %0, {%1, %2};" : "=l"(r) : "f"(x), "f"(y)); return r;
}
__device__ __forceinline__ void up2(u64 p, float &x, float &y) {
    asm("mov.b64 {%0, %1}, %2;" : "=f"(x), "=f"(y) : "l"(p));
}
__device__ __forceinline__ u64 ffma2(u64 a, u64 b, u64 c) {
    u64 d; asm("fma.rn.f32x2 %0, %1, %2, %3;" : "=l"(d) : "l"(a), "l"(b), "l"(c));
    return d;
}
__device__ __forceinline__ u64 fadd2(u64 a, u64 b) {
    u64 d; asm("add.rn.f32x2 %0, %1, %2;" : "=l"(d) : "l"(a), "l"(b)); return d;
}

// fast tanh: 1 - 2/(e^{2x}+1); MUFU-based, ~1e-7 rel err, correct saturation.
__device__ __forceinline__ float tanh_fast(float x) {
    float e = __expf(2.0f * x);
    return 1.0f - __fdividef(2.0f, e + 1.0f);
}

__device__ __forceinline__ u32 smem_u32(const void *p) {
    u32 a;
    asm("{ .reg .u64 t; cvta.to.shared.u64 t, %1; cvt.u32.u64 %0, t; }"
        : "=r"(a) : "l"(p));
    return a;
}
__device__ __forceinline__ u32 mapa32(u32 addr, u32 rank) {
    u32 r;
    asm("mapa.shared::cluster.u32 %0, %1, %2;" : "=r"(r) : "r"(addr), "r"(rank));
    return r;
}
__device__ __forceinline__ void st_remote16(u32 addr, u64 x, u64 y) {
    asm volatile("st.shared::cluster.u64 [%0], %1;" :: "r"(addr), "l"(x) : "memory");
    asm volatile("st.shared::cluster.u64 [%0], %1;" :: "r"(addr + 8), "l"(y) : "memory");
}
__device__ __forceinline__ void arrive_remote(u32 rmbar) {
    asm volatile("mbarrier.arrive.release.cluster.shared::cluster.b64 _, [%0];"
                 :: "r"(rmbar) : "memory");
}
__device__ __forceinline__ void wait_parity_cluster(u32 mbar, u32 ph) {
    asm volatile(
        "{\n\t"
        ".reg .pred P;\n"
        "WLOOP%=:\n\t"
        "mbarrier.try_wait.parity.acquire.cluster.shared::cta.b64 P, [%0], %1;\n\t"
        "@!P bra WLOOP%=;\n\t"
        "}"
        :: "r"(mbar), "r"(ph) : "memory");
}
__device__ __forceinline__ void cluster_sync() {
    asm volatile("barrier.cluster.arrive.aligned;" ::: "memory");
    asm volatile("barrier.cluster.wait.aligned;" ::: "memory");
}

// store packed row-pairs (one STS.128)
__device__ __forceinline__ void store_p(ulonglong2 *dst, float v0, float v1,
                                        float v2, float v3)
{
    ulonglong2 d;
    d.x = pk2(v0, v1);
    d.y = pk2(v2, v3);
    *dst = d;
}

// ---------------------------------------------------------------------------
// thread computes 4 output columns [c0, c0+4) over K-slice s (KSPAN rows).
// per k: 1 LDS.128 + 1 LDG.128 + 4 dup MOV + 8 FFMA2 (16 MACs).
// ---------------------------------------------------------------------------
template <int KSPAN, int WSTRIDE>
__device__ __forceinline__ void gemm_slice(const ulonglong2 *__restrict__ in,
                                           const float *__restrict__ W,
                                           ulonglong2 *__restrict__ sPart,
                                           int s, int c0)
{
    const ulonglong2 *ip = in + s * KSPAN;
    const float *wp = W + (size_t)(s * KSPAN) * WSTRIDE + c0;

    u64 a00 = 0, a01 = 0;   // col c0  : (r0,r1), (r2,r3)
    u64 a10 = 0, a11 = 0;   // col c0+1
    u64 a20 = 0, a21 = 0;   // col c0+2
    u64 a30 = 0, a31 = 0;   // col c0+3
#pragma unroll 4
    for (int k = 0; k < KSPAN; ++k) {
        ulonglong2 a = ip[k];                      // LDS.128 broadcast
        ulonglong2 w = *reinterpret_cast<const ulonglong2 *>(wp + (size_t)k * WSTRIDE);
        float w0, w1, w2, w3;
        up2(w.x, w0, w1); up2(w.y, w2, w3);
        u64 W0 = pk2(w0, w0), W1 = pk2(w1, w1);
        u64 W2 = pk2(w2, w2), W3 = pk2(w3, w3);
        a00 = ffma2(a.x, W0, a00);  a01 = ffma2(a.y, W0, a01);
        a10 = ffma2(a.x, W1, a10);  a11 = ffma2(a.y, W1, a11);
        a20 = ffma2(a.x, W2, a20);  a21 = ffma2(a.y, W2, a21);
        a30 = ffma2(a.x, W3, a30);  a31 = ffma2(a.y, W3, a31);
    }
    ulonglong2 *base = sPart + s * NC;
    ulonglong2 v;
    v.x = a00; v.y = a01; base[c0]     = v;
    v.x = a10; v.y = a11; base[c0 + 1] = v;
    v.x = a20; v.y = a21; base[c0 + 2] = v;
    v.x = a30; v.y = a31; base[c0 + 3] = v;
}

// Sum NSL partial slices for column c (+ bias) -> ((r0,r1),(r2,r3))
__device__ __forceinline__ ulonglong2 combineN(const ulonglong2 *__restrict__ sPart,
                                               int c, float bias)
{
    ulonglong2 p0 = sPart[c];
    u64 sx = p0.x, sy = p0.y;
#pragma unroll
    for (int s = 1; s < NSL; ++s) {
        ulonglong2 p = sPart[s * NC + c];
        sx = fadd2(sx, p.x);
        sy = fadd2(sy, p.y);
    }
    u64 bb = pk2(bias, bias);
    ulonglong2 r; r.x = fadd2(sx, bb); r.y = fadd2(sy, bb);
    return r;
}

// ---------------------------------------------------------------------------
// One full MLP eval with cross-CTA K reduction on phase B.
// ---------------------------------------------------------------------------
template <int KSA>
__device__ __forceinline__ float4 mlp_eval(
    const ulonglong2 *__restrict__ in,
    const float *__restrict__ Wa, float ba,
    const float *__restrict__ Wb, float bb,
    ulonglong2 *__restrict__ sHid, ulonglong2 *__restrict__ sPart,
    ulonglong2 *__restrict__ sPeer,
    u32 peerBufAddr, u32 mbarAddr, u32 mbarPeerAddr,
    int t, int s, int c0, int &x)
{
    gemm_slice<KSA, HIDD>(in, Wa, sPart, s, c0);
    __syncthreads();
    if (t < NC) {   // combine A + tanh -> local sHid (one hid col per thread)
        ulonglong2 h = combineN(sPart, t, ba);
        float u0, u1, u2, u3;
        up2(h.x, u0, u1); up2(h.y, u2, u3);
        store_p(&sHid[t], tanh_fast(u0), tanh_fast(u1),
                          tanh_fast(u2), tanh_fast(u3));
    }
    __syncthreads();
    gemm_slice<HHALF / NSL, LAT>(sHid, Wb, sPart, s, c0);
    __syncthreads();

    float4 res = make_float4(0.f, 0.f, 0.f, 0.f);
    const int buf = x & 1;
    if (t < NC) {
        ulonglong2 p = combineN(sPart, t, 0.f);          // local K-half partial
        st_remote16(peerBufAddr + (u32)(buf * NC + t) * 16u, p.x, p.y);
        arrive_remote(mbarPeerAddr);
        wait_parity_cluster(mbarAddr, (u32)buf);
        ulonglong2 q = sPeer[buf * NC + t];
        u64 bb2 = pk2(bb, bb);
        u64 sx = fadd2(fadd2(p.x, q.x), bb2);
        u64 sy = fadd2(fadd2(p.y, q.y), bb2);
        up2(sx, res.x, res.y);
        up2(sy, res.z, res.w);
    }
    x++;
    return res;
}

// ---------------------------------------------------------------------------
__global__ void __launch_bounds__(TPB, 1) __cluster_dims__(2, 1, 1)
odernn_kernel(const float *__restrict__ dataset,    // [B, T, OBS]
              const float *__restrict__ timestamps, // [B, T]
              const float *__restrict__ W1,  const float *__restrict__ b1,
              const float *__restrict__ W2,  const float *__restrict__ b2,
              const float *__restrict__ Wr1, const float *__restrict__ br1,
              const float *__restrict__ Wr2, const float *__restrict__ br2,
              float *__restrict__ out)               // [B, LAT]
{
    extern __shared__ char smem[];
    ulonglong2 *sC    = reinterpret_cast<ulonglong2 *>(smem);         // [320]
    ulonglong2 *sTmp  = sC + KRNN;                                    // [256]
    ulonglong2 *sHid  = sTmp + LAT;                                   // [256]
    ulonglong2 *sPart = sHid + HHALF;                                 // [16*256]
    ulonglong2 *sPeer = sPart + NSL * NC;                             // [2*256]
    float      *sH    = reinterpret_cast<float *>(sPeer + 2 * NC);    // [4]
    u64        *mbarp = reinterpret_cast<u64 *>(sH + 4);              // [1]

    const int t = threadIdx.x;
    u32 rank;
    asm("mov.u32 %0, %%cluster_ctarank;" : "=r"(rank));
    const u32 peerRank = rank ^ 1u;
    const int row0  = (blockIdx.x >> 1) * ROWS;
    const int hbase = (int)rank * HHALF;

    const int s  = t >> 6;            // K-slice 0..15
    const int c0 = 4 * (t & 63);      // 4-column group (64 groups = 256 cols)

    const u32 mbarAddr     = smem_u32(mbarp);
    const u32 mbarPeerAddr = mapa32(mbarAddr, peerRank);
    const u32 peerBufAddr  = mapa32(smem_u32(sPeer), peerRank);

    // weight slices for this rank
    const float *W1r  = W1  + hbase;                    // cols [hbase, +256)
    const float *Wr1r = Wr1 + hbase;
    const float *W2r  = W2  + (size_t)hbase * LAT;      // K-rows [hbase, +256)
    const float *Wr2r = Wr2 + (size_t)hbase * LAT;

    const float baO = (t < NC) ? b1[hbase + t]  : 0.f;
    const float baR = (t < NC) ? br1[hbase + t] : 0.f;
    const float bbO = (t < NC) ? b2[t]  : 0.f;
    const float bbR = (t < NC) ? br2[t] : 0.f;

    // ---- init: mbar, state = 0, x_{T-1} ----
    if (t == 0)
        asm volatile("mbarrier.init.shared.b64 [%0], %1;"
                     :: "r"(mbarAddr), "r"(NC) : "memory");
    if (t < LAT) store_p(&sC[t], 0.f, 0.f, 0.f, 0.f);
    if (t < LAT) {
        const int cc = t & (OBSD - 1);
        const int r  = t >> 6;     // entry = 4 floats r0..r3 in order
        float v = dataset[((row0 + r) * TSEQ + (TSEQ - 1)) * OBSD + cc];
        reinterpret_cast<float *>(&sC[LAT + cc])[r] = v;
    }
    __syncthreads();
    cluster_sync();   // mbar + state visible cluster-wide before first exchange

    int x = 0;        // exchange counter (uniform across both CTAs)

    // ---- initial RNN update: s += rnn(concat(s, x_{T-1})) ----
    {
        float4 o = mlp_eval<KRNN / NSL>(sC, Wr1r, baR, Wr2r, bbR,
                                        sHid, sPart, sPeer,
                                        peerBufAddr, mbarAddr, mbarPeerAddr,
                                        t, s, c0, x);
        if (t < NC) {
            ulonglong2 d = sC[t];
            float s0, s1, s2, s3;
            up2(d.x, s0, s1); up2(d.y, s2, s3);
            store_p(&sC[t], s0 + o.x, s1 + o.y, s2 + o.z, s3 + o.w);
        }
        __syncthreads();
    }

    // ---- reverse-time scan: i = T-2 .. 0 ----
    for (int i = TSEQ - 2; i >= 0; --i) {
        if (t < LAT) {
            const int cc = t & (OBSD - 1);
            const int r  = t >> 6;
            float v = dataset[((row0 + r) * TSEQ + i) * OBSD + cc];
            reinterpret_cast<float *>(&sC[LAT + cc])[r] = v;
        }
        if (t < ROWS) {
            const float *tsr = timestamps + (row0 + t) * TSEQ;
            sH[t] = (tsr[i] - tsr[i + 1]) / 3.0f;
        }
        __syncthreads();

        const float h0 = sH[0], h1 = sH[1], h2 = sH[2], h3 = sH[3];
        const float q0 = 0.5f * h0, q1 = 0.5f * h1, q2 = 0.5f * h2, q3 = 0.5f * h3;
        const float g0 = h0 / 6.0f, g1 = h1 / 6.0f, g2 = h2 / 6.0f, g3 = h3 / 6.0f;

#pragma unroll 1
        for (int sub = 0; sub < 3; ++sub) {
            float s0 = 0.f, s1 = 0.f, s2 = 0.f, s3 = 0.f;
            if (t < NC) {
                ulonglong2 d = sC[t];
                up2(d.x, s0, s1); up2(d.y, s2, s3);
            }
            float a0 = 0.f, a1 = 0.f, a2 = 0.f, a3 = 0.f;

            // k1
            float4 k = mlp_eval<LAT / NSL>(sC, W1r, baO, W2r, bbO,
                                           sHid, sPart, sPeer,
                                           peerBufAddr, mbarAddr, mbarPeerAddr,
                                           t, s, c0, x);
            if (t < NC) {
                a0 = k.x; a1 = k.y; a2 = k.z; a3 = k.w;
                store_p(&sTmp[t], fmaf(q0, k.x, s0), fmaf(q1, k.y, s1),
                                  fmaf(q2, k.z, s2), fmaf(q3, k.w, s3));
            }
            __syncthreads();

            // k2
            k = mlp_eval<LAT / NSL>(sTmp, W1r, baO, W2r, bbO,
                                    sHid, sPart, sPeer,
                                    peerBufAddr, mbarAddr, mbarPeerAddr,
                                    t, s, c0, x);
            if (t < NC) {
                a0 += 2.f * k.x; a1 += 2.f * k.y; a2 += 2.f * k.z; a3 += 2.f * k.w;
                store_p(&sTmp[t], fmaf(q0, k.x, s0), fmaf(q1, k.y, s1),
                                  fmaf(q2, k.z, s2), fmaf(q3, k.w, s3));
            }
            __syncthreads();

            // k3
            k = mlp_eval<LAT / NSL>(sTmp, W1r, baO, W2r, bbO,
                                    sHid, sPart, sPeer,
                                    peerBufAddr, mbarAddr, mbarPeerAddr,
                                    t, s, c0, x);
            if (t < NC) {
                a0 += 2.f * k.x; a1 += 2.f * k.y; a2 += 2.f * k.z; a3 += 2.f * k.w;
                store_p(&sTmp[t], fmaf(h0, k.x, s0), fmaf(h1, k.y, s1),
                                  fmaf(h2, k.z, s2), fmaf(h3, k.w, s3));
            }
            __syncthreads();

            // k4 + state update
            k = mlp_eval<LAT / NSL>(sTmp, W1r, baO, W2r, bbO,
                                    sHid, sPart, sPeer,
                                    peerBufAddr, mbarAddr, mbarPeerAddr,
                                    t, s, c0, x);
            if (t < NC) {
                a0 += k.x; a1 += k.y; a2 += k.z; a3 += k.w;
                store_p(&sC[t], fmaf(g0, a0, s0), fmaf(g1, a1, s1),
                                fmaf(g2, a2, s2), fmaf(g3, a3, s3));
            }
            __syncthreads();
        }

        // ---- RNN update: s += rnn(concat(s, x_i)) ----
        {
            float4 o = mlp_eval<KRNN / NSL>(sC, Wr1r, baR, Wr2r, bbR,
                                            sHid, sPart, sPeer,
                                            peerBufAddr, mbarAddr, mbarPeerAddr,
                                            t, s, c0, x);
            if (t < NC) {
                ulonglong2 d = sC[t];
                float s0, s1, s2, s3;
                up2(d.x, s0, s1); up2(d.y, s2, s3);
                store_p(&sC[t], s0 + o.x, s1 + o.y, s2 + o.z, s3 + o.w);
            }
            __syncthreads();
        }
    }

    // ---- write final state (rank 0 only) ----
    if (rank == 0 && t < NC) {
        ulonglong2 d = sC[t];
        float s0, s1, s2, s3;
        up2(d.x, s0, s1); up2(d.y, s2, s3);
        out[(row0 + 0) * LAT + t] = s0;
        out[(row0 + 1) * LAT + t] = s1;
        out[(row0 + 2) * LAT + t] = s2;
        out[(row0 + 3) * LAT + t] = s3;
    }

    cluster_sync();   // no CTA exits while peer traffic may be in flight
}

// ---------------------------------------------------------------------------
extern "C" void kernel_launch(void* const* d_in, const int* in_sizes, int n_in,
                              void* d_out, int out_size)
{
    (void)in_sizes; (void)n_in; (void)out_size;
    const float* dataset    = (const float*)d_in[0];
    const float* timestamps = (const float*)d_in[1];
    const float* W1  = (const float*)d_in[2];
    const float* b1  = (const float*)d_in[3];
    const float* W2  = (const float*)d_in[4];
    const float* b2  = (const float*)d_in[5];
    const float* Wr1 = (const float*)d_in[6];
    const float* br1 = (const float*)d_in[7];
    const float* Wr2 = (const float*)d_in[8];
    const float* br2 = (const float*)d_in[9];
    float* out = (float*)d_out;

    const size_t smem = (KRNN + LAT + HHALF) * sizeof(ulonglong2)
                      + (NSL * NC + 2 * NC) * sizeof(ulonglong2)
                      + 4 * sizeof(float) + 2 * sizeof(u64) + 64;
    static int configured = 0;
    if (!configured) {
        cudaFuncSetAttribute(odernn_kernel,
                             cudaFuncAttributeMaxDynamicSharedMemorySize,
                             (int)smem);
        configured = 1;
    }
    odernn_kernel<<<NCTA, TPB, smem>>>(dataset, timestamps,
                                       W1, b1, W2, b2, Wr1, br1, Wr2, br2, out);
}

// round 16
// speedup vs baseline: 1.3690x; 1.3690x over previous
#include <cuda_runtime.h>
#include <cuda_bf16.h>
#include <stdint.h>
#include <math.h>

// RecognitionODERNN: B=256, T=96, OBS=64, LATENT=256, HID=512, N_SUB=3
//
// R16 = R12 (best: 2-CTA clusters x 64, 512 thr/CTA, 4 rows/cluster, DSMEM
// phase-B exchange, packed row-pair activations, LDG.128 weights, FFMA2)
// + (a) MUFU tanh_fast in the barrier-bracketed combine
// + (b) phase-B weight prefetch peeled ahead of the combine barrier.

#define TSEQ  96
#define OBSD  64
#define LAT   256
#define HIDD  512
#define KRNN  320
#define ROWS  4
#define TPB   512
#define NCTA  128
#define HHALF 256     // hid cols per CTA
#define NSL   8       // K slices per phase
#define NC    256     // output cols per phase per CTA
#define KSB   (HHALF / NSL)   // 32: phase-B K-span per slice

typedef unsigned long long u64;
typedef unsigned int u32;

__device__ __forceinline__ u64 pk2(float x, float y) {
    u64 r; asm("mov.b64 %0, {%1, %2};" : "=l"(r) : "f"(x), "f"(y)); return r;
}
__device__ __forceinline__ void up2(u64 p, float &x, float &y) {
    asm("mov.b64 {%0, %1}, %2;" : "=f"(x), "=f"(y) : "l"(p));
}
__device__ __forceinline__ u64 ffma2(u64 a, u64 b, u64 c) {
    u64 d; asm("fma.rn.f32x2 %0, %1, %2, %3;" : "=l"(d) : "l"(a), "l"(b), "l"(c));
    return d;
}
__device__ __forceinline__ u64 fadd2(u64 a, u64 b) {
    u64 d; asm("add.rn.f32x2 %0, %1, %2;" : "=l"(d) : "l"(a), "l"(b)); return d;
}

// fast tanh: 1 - 2/(e^{2x}+1); MUFU-based, ~1e-7 rel err, correct saturation.
__device__ __forceinline__ float tanh_fast(float x) {
    float e = __expf(2.0f * x);
    return 1.0f - __fdividef(2.0f, e + 1.0f);
}

__device__ __forceinline__ u32 smem_u32(const void *p) {
    u32 a;
    asm("{ .reg .u64 t; cvta.to.shared.u64 t, %1; cvt.u32.u64 %0, t; }"
        : "=r"(a) : "l"(p));
    return a;
}
__device__ __forceinline__ u32 mapa32(u32 addr, u32 rank) {
    u32 r;
    asm("mapa.shared::cluster.u32 %0, %1, %2;" : "=r"(r) : "r"(addr), "r"(rank));
    return r;
}
__device__ __forceinline__ void st_remote16(u32 addr, u64 x, u64 y) {
    asm volatile("st.shared::cluster.u64 [%0], %1;" :: "r"(addr), "l"(x) : "memory");
    asm volatile("st.shared::cluster.u64 [%0], %1;" :: "r"(addr + 8), "l"(y) : "memory");
}
__device__ __forceinline__ void arrive_remote(u32 rmbar) {
    asm volatile("mbarrier.arrive.release.cluster.shared::cluster.b64 _, [%0];"
                 :: "r"(rmbar) : "memory");
}
__device__ __forceinline__ void wait_parity_cluster(u32 mbar, u32 ph) {
    asm volatile(
        "{\n\t"
        ".reg .pred P;\n"
        "WLOOP%=:\n\t"
        "mbarrier.try_wait.parity.acquire.cluster.shared::cta.b64 P, [%0], %1;\n\t"
        "@!P bra WLOOP%=;\n\t"
        "}"
        :: "r"(mbar), "r"(ph) : "memory");
}
__device__ __forceinline__ void cluster_sync() {
    asm volatile("barrier.cluster.arrive.aligned;" ::: "memory");
    asm volatile("barrier.cluster.wait.aligned;" ::: "memory");
}

// store packed row-pairs (one STS.128)
__device__ __forceinline__ void store_p(ulonglong2 *dst, float v0, float v1,
                                        float v2, float v3)
{
    ulonglong2 d;
    d.x = pk2(v0, v1);
    d.y = pk2(v2, v3);
    *dst = d;
}

// ---------------------------------------------------------------------------
// thread computes 4 output columns [c0, c0+4) over K-slice s (KSPAN rows).
// per k: 1 LDS.128 + 1 LDG.128 + 4 dup MOV + 8 FFMA2 (16 MACs).
// ---------------------------------------------------------------------------
template <int KSPAN, int WSTRIDE>
__device__ __forceinline__ void gemm_slice(const ulonglong2 *__restrict__ in,
                                           const float *__restrict__ W,
                                           ulonglong2 *__restrict__ sPart,
                                           int s, int c0)
{
    const ulonglong2 *ip = in + s * KSPAN;
    const float *wp = W + (size_t)(s * KSPAN) * WSTRIDE + c0;

    u64 a00 = 0, a01 = 0;   // col c0  : (r0,r1), (r2,r3)
    u64 a10 = 0, a11 = 0;   // col c0+1
    u64 a20 = 0, a21 = 0;   // col c0+2
    u64 a30 = 0, a31 = 0;   // col c0+3
#pragma unroll 8
    for (int k = 0; k < KSPAN; ++k) {
        ulonglong2 a = ip[k];
        ulonglong2 w = *reinterpret_cast<const ulonglong2 *>(wp + (size_t)k * WSTRIDE);
        float w0, w1, w2, w3;
        up2(w.x, w0, w1); up2(w.y, w2, w3);
        u64 W0 = pk2(w0, w0), W1 = pk2(w1, w1);
        u64 W2 = pk2(w2, w2), W3 = pk2(w3, w3);
        a00 = ffma2(a.x, W0, a00);  a01 = ffma2(a.y, W0, a01);
        a10 = ffma2(a.x, W1, a10);  a11 = ffma2(a.y, W1, a11);
        a20 = ffma2(a.x, W2, a20);  a21 = ffma2(a.y, W2, a21);
        a30 = ffma2(a.x, W3, a30);  a31 = ffma2(a.y, W3, a31);
    }
    ulonglong2 *base = sPart + s * NC;
    ulonglong2 v;
    v.x = a00; v.y = a01; base[c0]     = v;
    v.x = a10; v.y = a11; base[c0 + 1] = v;
    v.x = a20; v.y = a21; base[c0 + 2] = v;
    v.x = a30; v.y = a31; base[c0 + 3] = v;
}

// Phase-B variant: first 4 weight rows arrive preloaded (fetched before the
// combine barrier so they fly during combine+tanh).
__device__ __forceinline__ void gemm_sliceB_pf(const ulonglong2 *__restrict__ in,
                                               const float *__restrict__ W,
                                               ulonglong2 *__restrict__ sPart,
                                               int s, int c0,
                                               ulonglong2 w0, ulonglong2 w1,
                                               ulonglong2 w2, ulonglong2 w3)
{
    const ulonglong2 *ip = in + s * KSB;
    const float *wp = W + (size_t)(s * KSB) * LAT + c0;

    u64 a00 = 0, a01 = 0, a10 = 0, a11 = 0;
    u64 a20 = 0, a21 = 0, a30 = 0, a31 = 0;

    // peeled k = 0..3 with preloaded weights
    ulonglong2 wk[4] = {w0, w1, w2, w3};
#pragma unroll
    for (int k = 0; k < 4; ++k) {
        ulonglong2 a = ip[k];
        float f0, f1, f2, f3;
        up2(wk[k].x, f0, f1); up2(wk[k].y, f2, f3);
        u64 W0 = pk2(f0, f0), W1 = pk2(f1, f1);
        u64 W2 = pk2(f2, f2), W3 = pk2(f3, f3);
        a00 = ffma2(a.x, W0, a00);  a01 = ffma2(a.y, W0, a01);
        a10 = ffma2(a.x, W1, a10);  a11 = ffma2(a.y, W1, a11);
        a20 = ffma2(a.x, W2, a20);  a21 = ffma2(a.y, W2, a21);
        a30 = ffma2(a.x, W3, a30);  a31 = ffma2(a.y, W3, a31);
    }
#pragma unroll 7
    for (int k = 4; k < KSB; ++k) {
        ulonglong2 a = ip[k];
        ulonglong2 w = *reinterpret_cast<const ulonglong2 *>(wp + (size_t)k * LAT);
        float f0, f1, f2, f3;
        up2(w.x, f0, f1); up2(w.y, f2, f3);
        u64 W0 = pk2(f0, f0), W1 = pk2(f1, f1);
        u64 W2 = pk2(f2, f2), W3 = pk2(f3, f3);
        a00 = ffma2(a.x, W0, a00);  a01 = ffma2(a.y, W0, a01);
        a10 = ffma2(a.x, W1, a10);  a11 = ffma2(a.y, W1, a11);
        a20 = ffma2(a.x, W2, a20);  a21 = ffma2(a.y, W2, a21);
        a30 = ffma2(a.x, W3, a30);  a31 = ffma2(a.y, W3, a31);
    }
    ulonglong2 *base = sPart + s * NC;
    ulonglong2 v;
    v.x = a00; v.y = a01; base[c0]     = v;
    v.x = a10; v.y = a11; base[c0 + 1] = v;
    v.x = a20; v.y = a21; base[c0 + 2] = v;
    v.x = a30; v.y = a31; base[c0 + 3] = v;
}

// Sum 8 partial slices for column c (+ bias) -> ((r0,r1),(r2,r3))
__device__ __forceinline__ ulonglong2 combine8(const ulonglong2 *__restrict__ sPart,
                                               int c, float bias)
{
    ulonglong2 p0 = sPart[c];
    u64 sx = p0.x, sy = p0.y;
#pragma unroll
    for (int s = 1; s < NSL; ++s) {
        ulonglong2 p = sPart[s * NC + c];
        sx = fadd2(sx, p.x);
        sy = fadd2(sy, p.y);
    }
    u64 bb = pk2(bias, bias);
    ulonglong2 r; r.x = fadd2(sx, bb); r.y = fadd2(sy, bb);
    return r;
}

// ---------------------------------------------------------------------------
// One full MLP eval with cross-CTA K reduction on phase B.
// ---------------------------------------------------------------------------
template <int KSA>
__device__ __forceinline__ float4 mlp_eval(
    const ulonglong2 *__restrict__ in,
    const float *__restrict__ Wa, float ba,
    const float *__restrict__ Wb, float bb,
    ulonglong2 *__restrict__ sHid, ulonglong2 *__restrict__ sPart,
    ulonglong2 *__restrict__ sPeer,
    u32 peerBufAddr, u32 mbarAddr, u32 mbarPeerAddr,
    int t, int s, int c0, int &x)
{
    gemm_slice<KSA, HIDD>(in, Wa, sPart, s, c0);
    __syncthreads();

    // prefetch phase-B weight rows k=0..3 — LDGs fly during combine+tanh
    const float *wpB = Wb + (size_t)(s * KSB) * LAT + c0;
    ulonglong2 w0 = *reinterpret_cast<const ulonglong2 *>(wpB);
    ulonglong2 w1 = *reinterpret_cast<const ulonglong2 *>(wpB + LAT);
    ulonglong2 w2 = *reinterpret_cast<const ulonglong2 *>(wpB + 2 * LAT);
    ulonglong2 w3 = *reinterpret_cast<const ulonglong2 *>(wpB + 3 * LAT);

    if (t < NC) {   // combine A + tanh -> local sHid (one hid col per thread)
        ulonglong2 h = combine8(sPart, t, ba);
        float u0, u1, u2, u3;
        up2(h.x, u0, u1); up2(h.y, u2, u3);
        store_p(&sHid[t], tanh_fast(u0), tanh_fast(u1),
                          tanh_fast(u2), tanh_fast(u3));
    }
    __syncthreads();
    gemm_sliceB_pf(sHid, Wb, sPart, s, c0, w0, w1, w2, w3);
    __syncthreads();

    float4 res = make_float4(0.f, 0.f, 0.f, 0.f);
    const int buf = x & 1;
    if (t < NC) {
        ulonglong2 p = combine8(sPart, t, 0.f);          // local K-half partial
        st_remote16(peerBufAddr + (u32)(buf * NC + t) * 16u, p.x, p.y);
        arrive_remote(mbarPeerAddr);
        wait_parity_cluster(mbarAddr, (u32)buf);
        ulonglong2 q = sPeer[buf * NC + t];
        u64 bb2 = pk2(bb, bb);
        u64 sx = fadd2(fadd2(p.x, q.x), bb2);
        u64 sy = fadd2(fadd2(p.y, q.y), bb2);
        up2(sx, res.x, res.y);
        up2(sy, res.z, res.w);
    }
    x++;
    return res;
}

// ---------------------------------------------------------------------------
__global__ void __launch_bounds__(TPB, 1) __cluster_dims__(2, 1, 1)
odernn_kernel(const float *__restrict__ dataset,    // [B, T, OBS]
              const float *__restrict__ timestamps, // [B, T]
              const float *__restrict__ W1,  const float *__restrict__ b1,
              const float *__restrict__ W2,  const float *__restrict__ b2,
              const float *__restrict__ Wr1, const float *__restrict__ br1,
              const float *__restrict__ Wr2, const float *__restrict__ br2,
              float *__restrict__ out)               // [B, LAT]
{
    extern __shared__ char smem[];
    ulonglong2 *sC    = reinterpret_cast<ulonglong2 *>(smem);         // [320]
    ulonglong2 *sTmp  = sC + KRNN;                                    // [256]
    ulonglong2 *sHid  = sTmp + LAT;                                   // [256]
    ulonglong2 *sPart = sHid + HHALF;                                 // [8*256]
    ulonglong2 *sPeer = sPart + NSL * NC;                             // [2*256]
    float      *sH    = reinterpret_cast<float *>(sPeer + 2 * NC);    // [4]
    u64        *mbarp = reinterpret_cast<u64 *>(sH + 4);              // [1]

    const int t = threadIdx.x;
    u32 rank;
    asm("mov.u32 %0, %%cluster_ctarank;" : "=r"(rank));
    const u32 peerRank = rank ^ 1u;
    const int row0  = (blockIdx.x >> 1) * ROWS;
    const int hbase = (int)rank * HHALF;

    const int s  = t >> 6;            // K-slice 0..7
    const int c0 = 4 * (t & 63);      // 4-column group

    const u32 mbarAddr     = smem_u32(mbarp);
    const u32 mbarPeerAddr = mapa32(mbarAddr, peerRank);
    const u32 peerBufAddr  = mapa32(smem_u32(sPeer), peerRank);

    // weight slices for this rank
    const float *W1r  = W1  + hbase;                    // cols [hbase, +256)
    const float *Wr1r = Wr1 + hbase;
    const float *W2r  = W2  + (size_t)hbase * LAT;      // K-rows [hbase, +256)
    const float *Wr2r = Wr2 + (size_t)hbase * LAT;

    const float baO = (t < NC) ? b1[hbase + t]  : 0.f;
    const float baR = (t < NC) ? br1[hbase + t] : 0.f;
    const float bbO = (t < NC) ? b2[t]  : 0.f;
    const float bbR = (t < NC) ? br2[t] : 0.f;

    // ---- init: mbar, state = 0, x_{T-1} ----
    if (t == 0)
        asm volatile("mbarrier.init.shared.b64 [%0], %1;"
                     :: "r"(mbarAddr), "r"(NC) : "memory");
    if (t < LAT) store_p(&sC[t], 0.f, 0.f, 0.f, 0.f);
    if (t < LAT) {
        const int cc = t & (OBSD - 1);
        const int r  = t >> 6;     // entry = 4 floats r0..r3 in order
        float v = dataset[((row0 + r) * TSEQ + (TSEQ - 1)) * OBSD + cc];
        reinterpret_cast<float *>(&sC[LAT + cc])[r] = v;
    }
    __syncthreads();
    cluster_sync();   // mbar + state visible cluster-wide before first exchange

    int x = 0;        // exchange counter (uniform across both CTAs)

    // ---- initial RNN update: s += rnn(concat(s, x_{T-1})) ----
    {
        float4 o = mlp_eval<KRNN / NSL>(sC, Wr1r, baR, Wr2r, bbR,
                                        sHid, sPart, sPeer,
                                        peerBufAddr, mbarAddr, mbarPeerAddr,
                                        t, s, c0, x);
        if (t < NC) {
            ulonglong2 d = sC[t];
            float s0, s1, s2, s3;
            up2(d.x, s0, s1); up2(d.y, s2, s3);
            store_p(&sC[t], s0 + o.x, s1 + o.y, s2 + o.z, s3 + o.w);
        }
        __syncthreads();
    }

    // ---- reverse-time scan: i = T-2 .. 0 ----
    for (int i = TSEQ - 2; i >= 0; --i) {
        if (t < LAT) {
            const int cc = t & (OBSD - 1);
            const int r  = t >> 6;
            float v = dataset[((row0 + r) * TSEQ + i) * OBSD + cc];
            reinterpret_cast<float *>(&sC[LAT + cc])[r] = v;
        }
        if (t < ROWS) {
            const float *tsr = timestamps + (row0 + t) * TSEQ;
            sH[t] = (tsr[i] - tsr[i + 1]) / 3.0f;
        }
        __syncthreads();

        const float h0 = sH[0], h1 = sH[1], h2 = sH[2], h3 = sH[3];
        const float q0 = 0.5f * h0, q1 = 0.5f * h1, q2 = 0.5f * h2, q3 = 0.5f * h3;
        const float g0 = h0 / 6.0f, g1 = h1 / 6.0f, g2 = h2 / 6.0f, g3 = h3 / 6.0f;

#pragma unroll 1
        for (int sub = 0; sub < 3; ++sub) {
            float s0 = 0.f, s1 = 0.f, s2 = 0.f, s3 = 0.f;
            if (t < NC) {
                ulonglong2 d = sC[t];
                up2(d.x, s0, s1); up2(d.y, s2, s3);
            }
            float a0 = 0.f, a1 = 0.f, a2 = 0.f, a3 = 0.f;

            // k1
            float4 k = mlp_eval<LAT / NSL>(sC, W1r, baO, W2r, bbO,
                                           sHid, sPart, sPeer,
                                           peerBufAddr, mbarAddr, mbarPeerAddr,
                                           t, s, c0, x);
            if (t < NC) {
                a0 = k.x; a1 = k.y; a2 = k.z; a3 = k.w;
                store_p(&sTmp[t], fmaf(q0, k.x, s0), fmaf(q1, k.y, s1),
                                  fmaf(q2, k.z, s2), fmaf(q3, k.w, s3));
            }
            __syncthreads();

            // k2
            k = mlp_eval<LAT / NSL>(sTmp, W1r, baO, W2r, bbO,
                                    sHid, sPart, sPeer,
                                    peerBufAddr, mbarAddr, mbarPeerAddr,
                                    t, s, c0, x);
            if (t < NC) {
                a0 += 2.f * k.x; a1 += 2.f * k.y; a2 += 2.f * k.z; a3 += 2.f * k.w;
                store_p(&sTmp[t], fmaf(q0, k.x, s0), fmaf(q1, k.y, s1),
                                  fmaf(q2, k.z, s2), fmaf(q3, k.w, s3));
            }
            __syncthreads();

            // k3
            k = mlp_eval<LAT / NSL>(sTmp, W1r, baO, W2r, bbO,
                                    sHid, sPart, sPeer,
                                    peerBufAddr, mbarAddr, mbarPeerAddr,
                                    t, s, c0, x);
            if (t < NC) {
                a0 += 2.f * k.x; a1 += 2.f * k.y; a2 += 2.f * k.z; a3 += 2.f * k.w;
                store_p(&sTmp[t], fmaf(h0, k.x, s0), fmaf(h1, k.y, s1),
                                  fmaf(h2, k.z, s2), fmaf(h3, k.w, s3));
            }
            __syncthreads();

            // k4 + state update
            k = mlp_eval<LAT / NSL>(sTmp, W1r, baO, W2r, bbO,
                                    sHid, sPart, sPeer,
                                    peerBufAddr, mbarAddr, mbarPeerAddr,
                                    t, s, c0, x);
            if (t < NC) {
                a0 += k.x; a1 += k.y; a2 += k.z; a3 += k.w;
                store_p(&sC[t], fmaf(g0, a0, s0), fmaf(g1, a1, s1),
                                fmaf(g2, a2, s2), fmaf(g3, a3, s3));
            }
            __syncthreads();
        }

        // ---- RNN update: s += rnn(concat(s, x_i)) ----
        {
            float4 o = mlp_eval<KRNN / NSL>(sC, Wr1r, baR, Wr2r, bbR,
                                            sHid, sPart, sPeer,
                                            peerBufAddr, mbarAddr, mbarPeerAddr,
                                            t, s, c0, x);
            if (t < NC) {
                ulonglong2 d = sC[t];
                float s0, s1, s2, s3;
                up2(d.x, s0, s1); up2(d.y, s2, s3);
                store_p(&sC[t], s0 + o.x, s1 + o.y, s2 + o.z, s3 + o.w);
            }
            __syncthreads();
        }
    }

    // ---- write final state (rank 0 only) ----
    if (rank == 0 && t < NC) {
        ulonglong2 d = sC[t];
        float s0, s1, s2, s3;
        up2(d.x, s0, s1); up2(d.y, s2, s3);
        out[(row0 + 0) * LAT + t] = s0;
        out[(row0 + 1) * LAT + t] = s1;
        out[(row0 + 2) * LAT + t] = s2;
        out[(row0 + 3) * LAT + t] = s3;
    }

    cluster_sync();   // no CTA exits while peer traffic may be in flight
}

// ---------------------------------------------------------------------------
extern "C" void kernel_launch(void* const* d_in, const int* in_sizes, int n_in,
                              void* d_out, int out_size)
{
    (void)in_sizes; (void)n_in; (void)out_size;
    const float* dataset    = (const float*)d_in[0];
    const float* timestamps = (const float*)d_in[1];
    const float* W1  = (const float*)d_in[2];
    const float* b1  = (const float*)d_in[3];
    const float* W2  = (const float*)d_in[4];
    const float* b2  = (const float*)d_in[5];
    const float* Wr1 = (const float*)d_in[6];
    const float* br1 = (const float*)d_in[7];
    const float* Wr2 = (const float*)d_in[8];
    const float* br2 = (const float*)d_in[9];
    float* out = (float*)d_out;

    const size_t smem = (KRNN + LAT + HHALF) * sizeof(ulonglong2)
                      + (NSL * NC + 2 * NC) * sizeof(ulonglong2)
                      + 4 * sizeof(float) + 2 * sizeof(u64) + 64;
    static int configured = 0;
    if (!configured) {
        cudaFuncSetAttribute(odernn_kernel,
                             cudaFuncAttributeMaxDynamicSharedMemorySize,
                             (int)smem);
        configured = 1;
    }
    odernn_kernel<<<NCTA, TPB, smem>>>(dataset, timestamps,
                                       W1, b1, W2, b2, Wr1, br1, Wr2, br2, out);
}